// round 12
// baseline (speedup 1.0000x reference)
#include <cuda_runtime.h>
#include <cuda_bf16.h>
#include <math.h>

#define DIMS 64
#define MAXB 8192
#define KCAT 192          // [hi(64) | lo(64) | hi(64)] x [hi | hi | lo]
#define CH_BYTES 18432    // 128 rows x 144B per tile-chunk
#define SMEM_BYTES (2 * 2 * CH_BYTES)   // 73728 B
#define CAPR 1024         // per-row candidate capacity
#define NOPUSH 0xffffffffu

// Scratch (static device allocations are the sanctioned scratch mechanism).
static __device__ unsigned g_tmin[(size_t)MAXB * 64];         // per-(row,tile) min
static __device__ unsigned g_tub[MAXB];                       // per-row bound
static __device__ unsigned g_candv[(size_t)MAXB * CAPR];      // 32 MB
static __device__ int      g_candj[(size_t)MAXB * CAPR];      // 32 MB
static __device__ int      g_candn[MAXB];
static __device__ float g_sq[MAXB];
static __device__ int   g_hard[MAXB];
static __device__ int   g_gcounts[64];
static __device__ __nv_bfloat16 g_Acat[(size_t)MAXB * KCAT];  // 3.1 MB
static __device__ __nv_bfloat16 g_Bcat[(size_t)MAXB * KCAT];  // 3.1 MB

// ---------------------------------------------------------------------------
// Split fp32 -> bf16 hi+lo, build concatenated operands:
//   dot(Acat_i, Bcat_j) = hi.hi + lo.hi + hi.lo  (= x.y - lo.lo, |lo.lo|~1e-7)
// Also zeroes per-launch counters (graph-replay safe).
// ---------------------------------------------------------------------------
__global__ void convert_kernel(const float* __restrict__ E, int B) {
    if (blockIdx.x == 0 && threadIdx.x < 64) g_gcounts[threadIdx.x] = 0;
    int idx = blockIdx.x * blockDim.x + threadIdx.x;
    if (idx < B) g_candn[idx] = 0;
    if (idx >= B * DIMS) return;
    int i = idx >> 6, d = idx & 63;
    float x = E[idx];
    __nv_bfloat16 hi = __float2bfloat16(x);
    __nv_bfloat16 lo = __float2bfloat16(x - __bfloat162float(hi));
    size_t base = (size_t)i * KCAT;
    g_Acat[base + d]       = hi;
    g_Acat[base + 64 + d]  = lo;
    g_Acat[base + 128 + d] = hi;
    g_Bcat[base + d]       = hi;
    g_Bcat[base + 64 + d]  = hi;
    g_Bcat[base + 128 + d] = lo;
}

// ---------------------------------------------------------------------------
// Per-row: squared norm, argmax/max of categorical, global cluster counts.
// ---------------------------------------------------------------------------
__global__ void stats_kernel(const float* __restrict__ E,
                             const float* __restrict__ Cat,
                             float* __restrict__ out_maxg,
                             int B, int C) {
    int warp = (blockIdx.x * blockDim.x + threadIdx.x) >> 5;
    int lane = threadIdx.x & 31;
    if (warp >= B) return;

    float v0 = E[(size_t)warp * DIMS + lane];
    float v1 = E[(size_t)warp * DIMS + 32 + lane];
    float s = v0 * v0 + v1 * v1;
    #pragma unroll
    for (int off = 16; off; off >>= 1) s += __shfl_xor_sync(0xffffffffu, s, off);

    float mv = -INFINITY;
    int   mi = 0x7fffffff;
    for (int c = lane; c < C; c += 32) {
        float x = Cat[(size_t)warp * C + c];
        if (x > mv) { mv = x; mi = c; }
    }
    #pragma unroll
    for (int off = 16; off; off >>= 1) {
        float ov = __shfl_xor_sync(0xffffffffu, mv, off);
        int   oi = __shfl_xor_sync(0xffffffffu, mi, off);
        if (ov > mv || (ov == mv && oi < mi)) { mv = ov; mi = oi; }
    }

    if (lane == 0) {
        g_sq[warp]   = s;
        g_hard[warp] = mi;
        out_maxg[warp] = mv;
        atomicAdd(&g_gcounts[mi], 1);
    }
}

// ---------------------------------------------------------------------------
__device__ __forceinline__ void ldsm_x4(unsigned& r0, unsigned& r1,
                                        unsigned& r2, unsigned& r3, unsigned a) {
    asm volatile("ldmatrix.sync.aligned.m8n8.x4.shared.b16 {%0,%1,%2,%3}, [%4];"
                 : "=r"(r0), "=r"(r1), "=r"(r2), "=r"(r3) : "r"(a));
}
__device__ __forceinline__ void cp16(unsigned saddr, const void* gaddr) {
    asm volatile("cp.async.cg.shared.global [%0], [%1], 16;"
                 :: "r"(saddr), "l"(gaddr));
}
#define MMA_BF16(ACC, A, B0, B1)                                             \
    asm volatile(                                                            \
        "mma.sync.aligned.m16n8k16.row.col.f32.bf16.bf16.f32 "               \
        "{%0,%1,%2,%3}, {%4,%5,%6,%7}, {%8,%9}, {%0,%1,%2,%3};\n"            \
        : "+f"((ACC)[0]), "+f"((ACC)[1]), "+f"((ACC)[2]), "+f"((ACC)[3])     \
        : "r"((A)[0]), "r"((A)[1]), "r"((A)[2]), "r"((A)[3]),                \
          "r"(B0), "r"(B1))

// Triangular block decode
__device__ __forceinline__ void tri_decode(int x, int& bi, int& bj) {
    bi = (int)((sqrtf(8.0f * (float)x + 1.0f) - 1.0f) * 0.5f);
    while ((bi + 1) * (bi + 2) / 2 <= x) ++bi;
    while (bi * (bi + 1) / 2 > x) --bi;
    bj = x - bi * (bi + 1) / 2;
}

// ---------------------------------------------------------------------------
// Shared 128x128 tile GEMM mainloop (double-buffered cp.async, ldmatrix).
// Leaves the 64-value accumulator in acc (proven R8 structure).
// ---------------------------------------------------------------------------
__device__ __forceinline__ void compute_tile(int i0, int j0, int tid,
                                             unsigned sbase,
                                             float acc[2][8][4]) {
    int wid = tid >> 5, lane = tid & 31;
    int m0 = (wid >> 1) * 32;
    int n0 = (wid & 1) * 64;

    const char* gA = (const char*)g_Acat;
    const char* gB = (const char*)g_Bcat;

    unsigned aoff = (unsigned)(m0 + (lane & 15)) * 144 + ((lane >> 4) * 16);
    unsigned boff = (unsigned)(n0 + (lane & 7) + ((lane >> 4) << 3)) * 144
                  + (((lane >> 3) & 1) * 16);

    #pragma unroll
    for (int mt = 0; mt < 2; ++mt)
        #pragma unroll
        for (int nt = 0; nt < 8; ++nt)
            #pragma unroll
            for (int r = 0; r < 4; ++r) acc[mt][nt][r] = 0.f;

    #pragma unroll
    for (int pk = 0; pk < 2; ++pk) {       // preload chunks 0,1
        unsigned sA = sbase + (unsigned)(pk & 1) * (2 * CH_BYTES);
        unsigned sB = sA + CH_BYTES;
        #pragma unroll
        for (int it = 0; it < 4; ++it) {
            int idx = it * 256 + tid;
            int r = idx >> 3, c = idx & 7;
            cp16(sA + r * 144 + c * 16, gA + (size_t)(i0 + r) * 384 + pk * 128 + c * 16);
            cp16(sB + r * 144 + c * 16, gB + (size_t)(j0 + r) * 384 + pk * 128 + c * 16);
        }
        asm volatile("cp.async.commit_group;");
    }

    #pragma unroll
    for (int kc = 0; kc < 3; ++kc) {
        if (kc < 2) asm volatile("cp.async.wait_group 1;");
        else        asm volatile("cp.async.wait_group 0;");
        __syncthreads();

        unsigned sA = sbase + (unsigned)(kc & 1) * (2 * CH_BYTES);
        unsigned sB = sA + CH_BYTES;
        unsigned aab = sA + aoff, bab = sB + boff;

        #pragma unroll
        for (int ks = 0; ks < 4; ++ks) {
            unsigned kb = ks * 32;
            unsigned a0[4], a1[4];
            ldsm_x4(a0[0], a0[1], a0[2], a0[3], aab + kb);
            ldsm_x4(a1[0], a1[1], a1[2], a1[3], aab + kb + 16 * 144);
            #pragma unroll
            for (int p = 0; p < 4; ++p) {
                unsigned b0, b1, b2, b3;
                ldsm_x4(b0, b1, b2, b3, bab + kb + (unsigned)p * 16 * 144);
                MMA_BF16(acc[0][2 * p],     a0, b0, b1);
                MMA_BF16(acc[0][2 * p + 1], a0, b2, b3);
                MMA_BF16(acc[1][2 * p],     a1, b0, b1);
                MMA_BF16(acc[1][2 * p + 1], a1, b2, b3);
            }
        }
        __syncthreads();
        if (kc == 0) {                      // prefetch last chunk
            unsigned sA2 = sbase, sB2 = sbase + CH_BYTES;
            #pragma unroll
            for (int it = 0; it < 4; ++it) {
                int idx = it * 256 + tid;
                int r = idx >> 3, c = idx & 7;
                cp16(sA2 + r * 144 + c * 16, gA + (size_t)(i0 + r) * 384 + 256 + c * 16);
                cp16(sB2 + r * 144 + c * 16, gB + (size_t)(j0 + r) * 384 + 256 + c * 16);
            }
            asm volatile("cp.async.commit_group;");
        }
    }
}

// ---------------------------------------------------------------------------
// Pass A: tile minima only (no d2 materialization).
// ---------------------------------------------------------------------------
__global__ void __launch_bounds__(256, 2) minpass_kernel(int B) {
    extern __shared__ __align__(16) char smem[];
    __shared__ unsigned smin_row[128];
    __shared__ unsigned smin_col[128];

    int bi, bj; tri_decode(blockIdx.x, bi, bj);
    int i0 = bi * 128, j0 = bj * 128;
    int tid = threadIdx.x;
    int wid = tid >> 5, lane = tid & 31;
    int m0 = (wid >> 1) * 32, n0 = (wid & 1) * 64;

    if (tid < 128) smin_row[tid] = NOPUSH;
    else           smin_col[tid - 128] = NOPUSH;

    unsigned sbase;
    asm("{ .reg .u64 t; cvta.to.shared.u64 t, %1; cvt.u32.u64 %0, t; }"
        : "=r"(sbase) : "l"(smem));

    float acc[2][8][4];
    compute_tile(i0, j0, tid, sbase, acc);

    int g = lane >> 2, t = lane & 3;
    bool offdiag = (bi != bj);
    float cmin[8][2];
    #pragma unroll
    for (int nt = 0; nt < 8; ++nt) { cmin[nt][0] = INFINITY; cmin[nt][1] = INFINITY; }

    #pragma unroll
    for (int mt = 0; mt < 2; ++mt) {
        int ial = m0 + mt * 16 + g;
        int ia = i0 + ial;
        float si0 = g_sq[ia], si1 = g_sq[ia + 8];
        float rmin0 = INFINITY, rmin1 = INFINITY;
        #pragma unroll
        for (int nt = 0; nt < 8; ++nt) {
            int jc = j0 + n0 + nt * 8 + t * 2;
            float sj0 = g_sq[jc], sj1 = g_sq[jc + 1];
            float d00 = si0 + sj0 - 2.f * acc[mt][nt][0]; d00 = d00 > 0.f ? d00 : 0.f;
            float d01 = si0 + sj1 - 2.f * acc[mt][nt][1]; d01 = d01 > 0.f ? d01 : 0.f;
            float d10 = si1 + sj0 - 2.f * acc[mt][nt][2]; d10 = d10 > 0.f ? d10 : 0.f;
            float d11 = si1 + sj1 - 2.f * acc[mt][nt][3]; d11 = d11 > 0.f ? d11 : 0.f;
            rmin0 = fminf(rmin0, fminf(d00, d01));
            rmin1 = fminf(rmin1, fminf(d10, d11));
            cmin[nt][0] = fminf(cmin[nt][0], fminf(d00, d10));
            cmin[nt][1] = fminf(cmin[nt][1], fminf(d01, d11));
        }
        rmin0 = fminf(rmin0, __shfl_xor_sync(0xffffffffu, rmin0, 1));
        rmin0 = fminf(rmin0, __shfl_xor_sync(0xffffffffu, rmin0, 2));
        rmin1 = fminf(rmin1, __shfl_xor_sync(0xffffffffu, rmin1, 1));
        rmin1 = fminf(rmin1, __shfl_xor_sync(0xffffffffu, rmin1, 2));
        if (t == 0) {
            atomicMin(&smin_row[ial],     __float_as_uint(rmin0));
            atomicMin(&smin_row[ial + 8], __float_as_uint(rmin1));
        }
    }
    if (offdiag) {
        #pragma unroll
        for (int nt = 0; nt < 8; ++nt) {
            #pragma unroll
            for (int h = 0; h < 2; ++h) {
                float cm = cmin[nt][h];
                cm = fminf(cm, __shfl_xor_sync(0xffffffffu, cm, 4));
                cm = fminf(cm, __shfl_xor_sync(0xffffffffu, cm, 8));
                cm = fminf(cm, __shfl_xor_sync(0xffffffffu, cm, 16));
                if (g == 0)
                    atomicMin(&smin_col[n0 + nt * 8 + t * 2 + h], __float_as_uint(cm));
            }
        }
    }
    __syncthreads();
    if (tid < 128)       g_tmin[(size_t)(i0 + tid) * 64 + bj] = smin_row[tid];
    else if (offdiag)    g_tmin[(size_t)(j0 + tid - 128) * 64 + bi] = smin_col[tid - 128];
}

// ---------------------------------------------------------------------------
// Per-row bound: T_ub = exact kk-th smallest of the <=64 tile minima.
// ---------------------------------------------------------------------------
__global__ void tub_kernel(const int* __restrict__ kptr, int B) {
    int tid = threadIdx.x, lane = tid & 31, wid = tid >> 5;
    int row = blockIdx.x * 8 + wid;
    if (row >= B) return;

    int k = *kptr;
    if (k > B / 4) k = B / 4;
    int kk = k + 1;
    int ntile = B >> 7;

    unsigned tub = NOPUSH;
    if (kk <= ntile) {
        unsigned m0v = (lane      < ntile) ? g_tmin[(size_t)row * 64 + lane]      : NOPUSH;
        unsigned m1v = (lane + 32 < ntile) ? g_tmin[(size_t)row * 64 + lane + 32] : NOPUSH;
        int cls0 = 0, cle0 = 0, cls1 = 0, cle1 = 0;
        #pragma unroll
        for (int j = 0; j < 64; ++j) {
            unsigned b = __shfl_sync(0xffffffffu, (j < 32) ? m0v : m1v, j & 31);
            cls0 += (b < m0v);  cle0 += (b <= m0v);
            cls1 += (b < m1v);  cle1 += (b <= m1v);
        }
        bool sel0 = (cls0 < kk) && (cle0 >= kk);
        bool sel1 = (cls1 < kk) && (cle1 >= kk);
        unsigned bal0 = __ballot_sync(0xffffffffu, sel0);
        unsigned bal1 = __ballot_sync(0xffffffffu, sel1);
        if (bal0)      tub = __shfl_sync(0xffffffffu, m0v, __ffs(bal0) - 1);
        else if (bal1) tub = __shfl_sync(0xffffffffu, m1v, __ffs(bal1) - 1);
    }
    if (lane == 0) g_tub[row] = tub;
}

// ---------------------------------------------------------------------------
__device__ __forceinline__ void push_cand(int row, int col, unsigned bits) {
    int p = atomicAdd(&g_candn[row], 1);
    if (p < CAPR) {
        g_candv[(size_t)row * CAPR + p] = bits;
        g_candj[(size_t)row * CAPR + p] = col;
    }
}

// ---------------------------------------------------------------------------
// Pass B: identical GEMM recompute; push all d2 <= T_ub[row] candidates.
// ---------------------------------------------------------------------------
__global__ void __launch_bounds__(256, 2) candpass_kernel(int B) {
    extern __shared__ __align__(16) char smem[];

    int bi, bj; tri_decode(blockIdx.x, bi, bj);
    int i0 = bi * 128, j0 = bj * 128;
    int tid = threadIdx.x;
    int wid = tid >> 5, lane = tid & 31;
    int m0 = (wid >> 1) * 32, n0 = (wid & 1) * 64;

    unsigned sbase;
    asm("{ .reg .u64 t; cvta.to.shared.u64 t, %1; cvt.u32.u64 %0, t; }"
        : "=r"(sbase) : "l"(smem));

    float acc[2][8][4];
    compute_tile(i0, j0, tid, sbase, acc);

    int g = lane >> 2, t = lane & 3;
    bool offdiag = (bi != bj);

    #pragma unroll
    for (int mt = 0; mt < 2; ++mt) {
        int ia = i0 + m0 + mt * 16 + g;
        float si0 = g_sq[ia], si1 = g_sq[ia + 8];
        unsigned tA = g_tub[ia], tB = g_tub[ia + 8];
        #pragma unroll
        for (int nt = 0; nt < 8; ++nt) {
            int jc = j0 + n0 + nt * 8 + t * 2;
            float sj0 = g_sq[jc], sj1 = g_sq[jc + 1];
            float d00 = si0 + sj0 - 2.f * acc[mt][nt][0]; d00 = d00 > 0.f ? d00 : 0.f;
            float d01 = si0 + sj1 - 2.f * acc[mt][nt][1]; d01 = d01 > 0.f ? d01 : 0.f;
            float d10 = si1 + sj0 - 2.f * acc[mt][nt][2]; d10 = d10 > 0.f ? d10 : 0.f;
            float d11 = si1 + sj1 - 2.f * acc[mt][nt][3]; d11 = d11 > 0.f ? d11 : 0.f;
            unsigned b00 = __float_as_uint(d00), b01 = __float_as_uint(d01);
            unsigned b10 = __float_as_uint(d10), b11 = __float_as_uint(d11);
            if (tA != NOPUSH) {
                if (b00 <= tA) push_cand(ia, jc,     b00);
                if (b01 <= tA) push_cand(ia, jc + 1, b01);
            }
            if (tB != NOPUSH) {
                if (b10 <= tB) push_cand(ia + 8, jc,     b10);
                if (b11 <= tB) push_cand(ia + 8, jc + 1, b11);
            }
            if (offdiag) {
                unsigned tj0 = g_tub[jc], tj1 = g_tub[jc + 1];
                if (tj0 != NOPUSH) {
                    if (b00 <= tj0) push_cand(jc, ia,     b00);
                    if (b10 <= tj0) push_cand(jc, ia + 8, b10);
                }
                if (tj1 != NOPUSH) {
                    if (b01 <= tj1) push_cand(jc + 1, ia,     b01);
                    if (b11 <= tj1) push_cand(jc + 1, ia + 8, b11);
                }
            }
        }
    }
}

// ---------------------------------------------------------------------------
// Per-row (one warp each): exact kk-th among candidates, strict-< histogram,
// entropy. Fallback (kk > ntile or overflow; never hit at k=15): exact fp32
// recompute from E.
// ---------------------------------------------------------------------------
__global__ void __launch_bounds__(256) select2_kernel(const int* __restrict__ kptr,
                                                      const float* __restrict__ E,
                                                      float* __restrict__ out_ent,
                                                      int B, int C) {
    __shared__ int   counts[8][64];
    __shared__ float Erow[8][DIMS];

    int tid = threadIdx.x, lane = tid & 31, wid = tid >> 5;
    int row = blockIdx.x * 8 + wid;

    for (int c = lane; c < 64; c += 32) counts[wid][c] = 0;
    __syncwarp();
    if (row >= B) return;

    int k = *kptr;
    if (k > B / 4) k = B / 4;
    int kk = k + 1;

    unsigned tub = g_tub[row];
    int n = g_candn[row];
    const unsigned* cv = g_candv + (size_t)row * CAPR;
    const int*      cj = g_candj + (size_t)row * CAPR;
    bool fb = (tub == NOPUSH) || (n > CAPR);

    if (!fb) {
        unsigned kth;
        if (n <= 32) {
            unsigned c = (lane < n) ? cv[lane] : NOPUSH;
            int cls = 0, cle = 0;
            for (int j = 0; j < n; ++j) {
                unsigned b = __shfl_sync(0xffffffffu, c, j);
                cls += (b < c);
                cle += (b <= c);
            }
            bool sel = (cls < kk) && (cle >= kk);
            unsigned ball = __ballot_sync(0xffffffffu, sel);
            kth = __shfl_sync(0xffffffffu, c, __ffs(ball) - 1);
        } else {
            unsigned prefix = 0u;
            for (int b = 30; b >= 0; --b) {
                unsigned tc = prefix | (1u << b);
                int cc = 0;
                for (int p = lane; p < n; p += 32) cc += (cv[p] < tc);
                #pragma unroll
                for (int off = 16; off; off >>= 1) cc += __shfl_xor_sync(0xffffffffu, cc, off);
                if (cc < kk) prefix = tc;
            }
            kth = prefix;
        }
        for (int p = lane; p < n; p += 32)
            if (cv[p] < kth) atomicAdd(&counts[wid][g_hard[cj[p]]], 1);
    } else {
        // exact fp32 recompute path (correctness insurance; not expected)
        float sqi = g_sq[row];
        for (int d = lane; d < DIMS; d += 32) Erow[wid][d] = E[(size_t)row * DIMS + d];
        __syncwarp();
        unsigned prefix = 0u;
        for (int b = 30; b >= 0; --b) {
            unsigned tc = prefix | (1u << b);
            int cc = 0;
            for (int j = lane; j < B; j += 32) {
                const float* ej = E + (size_t)j * DIMS;
                float dot = 0.f;
                for (int d = 0; d < DIMS; ++d) dot += Erow[wid][d] * ej[d];
                float dd = sqi + g_sq[j] - 2.f * dot; dd = dd > 0.f ? dd : 0.f;
                cc += (__float_as_uint(dd) < tc);
            }
            #pragma unroll
            for (int off = 16; off; off >>= 1) cc += __shfl_xor_sync(0xffffffffu, cc, off);
            if (cc < kk) prefix = tc;
        }
        for (int j = lane; j < B; j += 32) {
            const float* ej = E + (size_t)j * DIMS;
            float dot = 0.f;
            for (int d = 0; d < DIMS; ++d) dot += Erow[wid][d] * ej[d];
            float dd = sqi + g_sq[j] - 2.f * dot; dd = dd > 0.f ? dd : 0.f;
            if (__float_as_uint(dd) < prefix) atomicAdd(&counts[wid][g_hard[j]], 1);
        }
    }
    __syncwarp();

    float c0 = (lane < C)      ? (float)counts[wid][lane]      : 0.f;
    float c1 = (lane + 32 < C) ? (float)counts[wid][lane + 32] : 0.f;
    float nn = c0 + c1;
    #pragma unroll
    for (int off = 16; off; off >>= 1) nn += __shfl_xor_sync(0xffffffffu, nn, off);
    float ni = (nn > 1.f) ? nn : 1.f;
    float b0 = c0 / ni, b1 = c1 / ni;
    float h = -b0 * logf(b0 + 1e-5f) - b1 * logf(b1 + 1e-5f);
    #pragma unroll
    for (int off = 16; off; off >>= 1) h += __shfl_xor_sync(0xffffffffu, h, off);
    if (lane == 0) out_ent[row] = h;
}

// ---------------------------------------------------------------------------
__global__ void finalize_kernel(float* __restrict__ out2, int B, int C) {
    int lane = threadIdx.x;
    float g  = (lane < C) ? (float)g_gcounts[lane] : 0.f;
    float gb = g / (float)B;
    float h  = -gb * logf(gb + 1e-5f);
    float p  = (lane < C && g > 0.f) ? 1.f : 0.f;
    #pragma unroll
    for (int off = 16; off; off >>= 1) {
        h += __shfl_xor_sync(0xffffffffu, h, off);
        p += __shfl_xor_sync(0xffffffffu, p, off);
    }
    if (lane == 0) { out2[0] = h; out2[1] = p; }
}

// ---------------------------------------------------------------------------
// Output layout (flattened reference tuple):
//   [0, B*64)            encodings passthrough
//   [B*64, B*64+B)       neighbourhood_entropy
//   [B*64+B]             cluster_size_entropy
//   [B*64+B+1]           n_populated
//   [B*64+B+2, +B)       max_groups
// ---------------------------------------------------------------------------
extern "C" void kernel_launch(void* const* d_in, const int* in_sizes, int n_in,
                              void* d_out, int out_size) {
    const float* E    = (const float*)d_in[0];
    const float* Cat  = (const float*)d_in[1];
    const int*   kptr = (const int*)d_in[2];

    int B = in_sizes[0] / DIMS;
    int C = in_sizes[1] / B;

    float* out      = (float*)d_out;
    float* out_ent  = out + (size_t)B * DIMS;
    float* out_sc   = out_ent + B;
    float* out_maxg = out_sc + 2;

    cudaMemcpyAsync(out, E, (size_t)B * DIMS * sizeof(float),
                    cudaMemcpyDeviceToDevice, 0);

    cudaFuncSetAttribute(minpass_kernel,
                         cudaFuncAttributeMaxDynamicSharedMemorySize, SMEM_BYTES);
    cudaFuncSetAttribute(candpass_kernel,
                         cudaFuncAttributeMaxDynamicSharedMemorySize, SMEM_BYTES);

    int nb = B / 128;
    int ntri = nb * (nb + 1) / 2;

    convert_kernel<<<(B * DIMS + 255) / 256, 256>>>(E, B);
    stats_kernel<<<(B * 32 + 255) / 256, 256>>>(E, Cat, out_maxg, B, C);
    minpass_kernel<<<ntri, 256, SMEM_BYTES>>>(B);
    tub_kernel<<<(B + 7) / 8, 256>>>(kptr, B);
    candpass_kernel<<<ntri, 256, SMEM_BYTES>>>(B);
    select2_kernel<<<(B + 7) / 8, 256>>>(kptr, E, out_ent, B, C);
    finalize_kernel<<<1, 32>>>(out_sc, B, C);
}

// round 13
// speedup vs baseline: 1.3975x; 1.3975x over previous
#include <cuda_runtime.h>
#include <cuda_bf16.h>
#include <math.h>

#define DIMS 64
#define MAXB 8192
#define KCAT 192          // [hi(64) | lo(64) | hi(64)] x [hi | hi | lo]
#define CH_BYTES 18432    // 128 rows x 144B per tile-chunk
#define SMEM_BYTES (2 * 2 * CH_BYTES)   // 73728 B
#define CAPW 256          // per-warp candidate capacity (expected ~20-40)
#define NOPUSH 0xffffffffu

// Scratch (static device allocations are the sanctioned scratch mechanism).
static __device__ float g_d2[(size_t)MAXB * (size_t)MAXB];    // 256 MB
static __device__ unsigned g_tmin[(size_t)MAXB * 64];         // 2 MB per-(row,tile) min
static __device__ float g_sq[MAXB];
static __device__ int   g_hard[MAXB];
static __device__ int   g_gcounts[64];
static __device__ __nv_bfloat16 g_Acat[(size_t)MAXB * KCAT];  // 3.1 MB
static __device__ __nv_bfloat16 g_Bcat[(size_t)MAXB * KCAT];  // 3.1 MB

// ---------------------------------------------------------------------------
// Split fp32 -> bf16 hi+lo, build concatenated operands:
//   dot(Acat_i, Bcat_j) = hi.hi + lo.hi + hi.lo  (= x.y - lo.lo, |lo.lo|~1e-7)
// Block 0 also zeroes the global cluster counters.
// ---------------------------------------------------------------------------
__global__ void convert_kernel(const float* __restrict__ E, int B) {
    if (blockIdx.x == 0 && threadIdx.x < 64) g_gcounts[threadIdx.x] = 0;
    int idx = blockIdx.x * blockDim.x + threadIdx.x;
    if (idx >= B * DIMS) return;
    int i = idx >> 6, d = idx & 63;
    float x = E[idx];
    __nv_bfloat16 hi = __float2bfloat16(x);
    __nv_bfloat16 lo = __float2bfloat16(x - __bfloat162float(hi));
    size_t base = (size_t)i * KCAT;
    g_Acat[base + d]       = hi;
    g_Acat[base + 64 + d]  = lo;
    g_Acat[base + 128 + d] = hi;
    g_Bcat[base + d]       = hi;
    g_Bcat[base + 64 + d]  = hi;
    g_Bcat[base + 128 + d] = lo;
}

// ---------------------------------------------------------------------------
// Per-row: squared norm, argmax/max of categorical, global cluster counts.
// ---------------------------------------------------------------------------
__global__ void stats_kernel(const float* __restrict__ E,
                             const float* __restrict__ Cat,
                             float* __restrict__ out_maxg,
                             int B, int C) {
    int warp = (blockIdx.x * blockDim.x + threadIdx.x) >> 5;
    int lane = threadIdx.x & 31;
    if (warp >= B) return;

    float v0 = E[(size_t)warp * DIMS + lane];
    float v1 = E[(size_t)warp * DIMS + 32 + lane];
    float s = v0 * v0 + v1 * v1;
    #pragma unroll
    for (int off = 16; off; off >>= 1) s += __shfl_xor_sync(0xffffffffu, s, off);

    float mv = -INFINITY;
    int   mi = 0x7fffffff;
    for (int c = lane; c < C; c += 32) {
        float x = Cat[(size_t)warp * C + c];
        if (x > mv) { mv = x; mi = c; }
    }
    #pragma unroll
    for (int off = 16; off; off >>= 1) {
        float ov = __shfl_xor_sync(0xffffffffu, mv, off);
        int   oi = __shfl_xor_sync(0xffffffffu, mi, off);
        if (ov > mv || (ov == mv && oi < mi)) { mv = ov; mi = oi; }
    }

    if (lane == 0) {
        g_sq[warp]   = s;
        g_hard[warp] = mi;
        out_maxg[warp] = mv;
        atomicAdd(&g_gcounts[mi], 1);
    }
}

// ---------------------------------------------------------------------------
__device__ __forceinline__ void ldsm_x4(unsigned& r0, unsigned& r1,
                                        unsigned& r2, unsigned& r3, unsigned a) {
    asm volatile("ldmatrix.sync.aligned.m8n8.x4.shared.b16 {%0,%1,%2,%3}, [%4];"
                 : "=r"(r0), "=r"(r1), "=r"(r2), "=r"(r3) : "r"(a));
}
__device__ __forceinline__ void cp16(unsigned saddr, const void* gaddr) {
    asm volatile("cp.async.cg.shared.global [%0], [%1], 16;"
                 :: "r"(saddr), "l"(gaddr));
}
#define MMA_BF16(ACC, A, B0, B1)                                             \
    asm volatile(                                                            \
        "mma.sync.aligned.m16n8k16.row.col.f32.bf16.bf16.f32 "               \
        "{%0,%1,%2,%3}, {%4,%5,%6,%7}, {%8,%9}, {%0,%1,%2,%3};\n"            \
        : "+f"((ACC)[0]), "+f"((ACC)[1]), "+f"((ACC)[2]), "+f"((ACC)[3])     \
        : "r"((A)[0]), "r"((A)[1]), "r"((A)[2]), "r"((A)[3]),                \
          "r"(B0), "r"(B1))

// ---------------------------------------------------------------------------
// Symmetric tensor-core GEMM (triangle-only grid), double-buffered cp.async
// pipeline. Epilogue: d2 stores (straight float2 + scattered mirror) and
// per-(row, column-tile) minima. [R10 configuration — measured 90 us]
// ---------------------------------------------------------------------------
__global__ void __launch_bounds__(256, 2) mma_gemm_kernel(int B) {
    extern __shared__ __align__(16) char smem[];
    __shared__ unsigned smin_row[128];
    __shared__ unsigned smin_col[128];

    // triangular decode: block x -> (bi >= bj)
    int x = blockIdx.x;
    int bi = (int)((sqrtf(8.0f * (float)x + 1.0f) - 1.0f) * 0.5f);
    while ((bi + 1) * (bi + 2) / 2 <= x) ++bi;
    while (bi * (bi + 1) / 2 > x) --bi;
    int bj = x - bi * (bi + 1) / 2;
    int i0 = bi * 128, j0 = bj * 128;

    int tid = threadIdx.x;
    int wid = tid >> 5, lane = tid & 31;
    int m0 = (wid >> 1) * 32;     // warp_m: 0..3
    int n0 = (wid & 1) * 64;      // warp_n: 0..1

    if (tid < 128) smin_row[tid] = NOPUSH;
    else           smin_col[tid - 128] = NOPUSH;

    unsigned sbase;
    asm("{ .reg .u64 t; cvta.to.shared.u64 t, %1; cvt.u32.u64 %0, t; }"
        : "=r"(sbase) : "l"(smem));
    const char* gA = (const char*)g_Acat;
    const char* gB = (const char*)g_Bcat;

    unsigned aoff = (unsigned)(m0 + (lane & 15)) * 144 + ((lane >> 4) * 16);
    unsigned boff = (unsigned)(n0 + (lane & 7) + ((lane >> 4) << 3)) * 144
                  + (((lane >> 3) & 1) * 16);

    float acc[2][8][4];
    #pragma unroll
    for (int mt = 0; mt < 2; ++mt)
        #pragma unroll
        for (int nt = 0; nt < 8; ++nt)
            #pragma unroll
            for (int r = 0; r < 4; ++r) acc[mt][nt][r] = 0.f;

    auto load_chunk = [&](int kc) {
        unsigned sA = sbase + (unsigned)(kc & 1) * (2 * CH_BYTES);
        unsigned sB = sA + CH_BYTES;
        #pragma unroll
        for (int it = 0; it < 4; ++it) {
            int idx = it * 256 + tid;
            int r = idx >> 3, c = idx & 7;
            cp16(sA + r * 144 + c * 16, gA + (size_t)(i0 + r) * 384 + kc * 128 + c * 16);
            cp16(sB + r * 144 + c * 16, gB + (size_t)(j0 + r) * 384 + kc * 128 + c * 16);
        }
        asm volatile("cp.async.commit_group;");
    };

    load_chunk(0);
    load_chunk(1);

    #pragma unroll
    for (int kc = 0; kc < 3; ++kc) {
        if (kc < 2) asm volatile("cp.async.wait_group 1;");
        else        asm volatile("cp.async.wait_group 0;");
        __syncthreads();

        unsigned sA = sbase + (unsigned)(kc & 1) * (2 * CH_BYTES);
        unsigned sB = sA + CH_BYTES;
        unsigned aab = sA + aoff, bab = sB + boff;

        #pragma unroll
        for (int ks = 0; ks < 4; ++ks) {
            unsigned kb = ks * 32;
            unsigned a0[4], a1[4];
            ldsm_x4(a0[0], a0[1], a0[2], a0[3], aab + kb);
            ldsm_x4(a1[0], a1[1], a1[2], a1[3], aab + kb + 16 * 144);
            #pragma unroll
            for (int p = 0; p < 4; ++p) {
                unsigned b0, b1, b2, b3;
                ldsm_x4(b0, b1, b2, b3, bab + kb + (unsigned)p * 16 * 144);
                MMA_BF16(acc[0][2 * p],     a0, b0, b1);
                MMA_BF16(acc[0][2 * p + 1], a0, b2, b3);
                MMA_BF16(acc[1][2 * p],     a1, b0, b1);
                MMA_BF16(acc[1][2 * p + 1], a1, b2, b3);
            }
        }
        __syncthreads();
        if (kc == 0) load_chunk(2);
    }

    // Epilogue: d2 = sq_i + sq_j - 2*dot (clamped to +0) + tile minima.
    int g = lane >> 2, t = lane & 3;
    bool offdiag = (bi != bj);
    float cmin[8][2];
    #pragma unroll
    for (int nt = 0; nt < 8; ++nt) { cmin[nt][0] = INFINITY; cmin[nt][1] = INFINITY; }

    #pragma unroll
    for (int mt = 0; mt < 2; ++mt) {
        int ial = m0 + mt * 16 + g;
        int ia = i0 + ial;
        float si0 = g_sq[ia], si1 = g_sq[ia + 8];
        float rmin0 = INFINITY, rmin1 = INFINITY;
        #pragma unroll
        for (int nt = 0; nt < 8; ++nt) {
            int jc = j0 + n0 + nt * 8 + t * 2;
            float sj0 = g_sq[jc], sj1 = g_sq[jc + 1];
            float d00 = si0 + sj0 - 2.f * acc[mt][nt][0]; d00 = d00 > 0.f ? d00 : 0.f;
            float d01 = si0 + sj1 - 2.f * acc[mt][nt][1]; d01 = d01 > 0.f ? d01 : 0.f;
            float d10 = si1 + sj0 - 2.f * acc[mt][nt][2]; d10 = d10 > 0.f ? d10 : 0.f;
            float d11 = si1 + sj1 - 2.f * acc[mt][nt][3]; d11 = d11 > 0.f ? d11 : 0.f;
            *(float2*)(g_d2 + (size_t)ia * B + jc)       = make_float2(d00, d01);
            *(float2*)(g_d2 + (size_t)(ia + 8) * B + jc) = make_float2(d10, d11);
            if (offdiag) {
                g_d2[(size_t)jc * B + ia]           = d00;
                g_d2[(size_t)(jc + 1) * B + ia]     = d01;
                g_d2[(size_t)jc * B + ia + 8]       = d10;
                g_d2[(size_t)(jc + 1) * B + ia + 8] = d11;
            }
            rmin0 = fminf(rmin0, fminf(d00, d01));
            rmin1 = fminf(rmin1, fminf(d10, d11));
            cmin[nt][0] = fminf(cmin[nt][0], fminf(d00, d10));
            cmin[nt][1] = fminf(cmin[nt][1], fminf(d01, d11));
        }
        rmin0 = fminf(rmin0, __shfl_xor_sync(0xffffffffu, rmin0, 1));
        rmin0 = fminf(rmin0, __shfl_xor_sync(0xffffffffu, rmin0, 2));
        rmin1 = fminf(rmin1, __shfl_xor_sync(0xffffffffu, rmin1, 1));
        rmin1 = fminf(rmin1, __shfl_xor_sync(0xffffffffu, rmin1, 2));
        if (t == 0) {
            atomicMin(&smin_row[ial],     __float_as_uint(rmin0));
            atomicMin(&smin_row[ial + 8], __float_as_uint(rmin1));
        }
    }
    if (offdiag) {
        #pragma unroll
        for (int nt = 0; nt < 8; ++nt) {
            #pragma unroll
            for (int h = 0; h < 2; ++h) {
                float cm = cmin[nt][h];
                cm = fminf(cm, __shfl_xor_sync(0xffffffffu, cm, 4));
                cm = fminf(cm, __shfl_xor_sync(0xffffffffu, cm, 8));
                cm = fminf(cm, __shfl_xor_sync(0xffffffffu, cm, 16));
                if (g == 0)
                    atomicMin(&smin_col[n0 + nt * 8 + t * 2 + h], __float_as_uint(cm));
            }
        }
    }
    __syncthreads();
    if (tid < 128)       g_tmin[(size_t)(i0 + tid) * 64 + bj] = smin_row[tid];
    else if (offdiag)    g_tmin[(size_t)(j0 + tid - 128) * 64 + bi] = smin_col[tid - 128];
}

// ---------------------------------------------------------------------------
// Warp-per-row selection + entropy (8 rows per 256-thread block; no block
// barriers, no idle warps). Per row:
//  1. T_ub = exact kk-th of the 64 tile minima (rank-trick)  [guaranteed UB]
//  2. ballot the tiles with min <= T_ub, gather only those (coalesced uint4)
//  3. warp-aggregated compaction into smem, exact kk-th, strict-< histogram
// Fallback (kk > ntile or overflow; never hit at k=15): exact radix over the
// materialized d2 row.
// ---------------------------------------------------------------------------
__global__ void __launch_bounds__(256) select3_kernel(const int* __restrict__ kptr,
                                                      float* __restrict__ out_ent,
                                                      int B, int C) {
    __shared__ unsigned sv[8][CAPW];
    __shared__ int      sj[8][CAPW];
    __shared__ int      counts[8][64];

    int tid = threadIdx.x, lane = tid & 31, wid = tid >> 5;
    int row = blockIdx.x * 8 + wid;

    counts[wid][lane] = 0;
    counts[wid][lane + 32] = 0;
    if (row >= B) return;

    int k = *kptr;
    if (k > B / 4) k = B / 4;
    int kk = k + 1;
    int ntile = B >> 7;

    const float* rowp = g_d2 + (size_t)row * B;
    unsigned m0v = (lane      < ntile) ? g_tmin[(size_t)row * 64 + lane]      : NOPUSH;
    unsigned m1v = (lane + 32 < ntile) ? g_tmin[(size_t)row * 64 + lane + 32] : NOPUSH;

    // ---- Phase 1: T_ub via 64-way rank-trick ----
    unsigned tub = NOPUSH;
    if (kk <= ntile) {
        int cls0 = 0, cle0 = 0, cls1 = 0, cle1 = 0;
        #pragma unroll
        for (int j = 0; j < 64; ++j) {
            unsigned b = __shfl_sync(0xffffffffu, (j < 32) ? m0v : m1v, j & 31);
            cls0 += (b < m0v);  cle0 += (b <= m0v);
            cls1 += (b < m1v);  cle1 += (b <= m1v);
        }
        bool sel0 = (cls0 < kk) && (cle0 >= kk);
        bool sel1 = (cls1 < kk) && (cle1 >= kk);
        unsigned bal0 = __ballot_sync(0xffffffffu, sel0);
        unsigned bal1 = __ballot_sync(0xffffffffu, sel1);
        if (bal0)      tub = __shfl_sync(0xffffffffu, m0v, __ffs(bal0) - 1);
        else if (bal1) tub = __shfl_sync(0xffffffffu, m1v, __ffs(bal1) - 1);
    }

    bool fb = (tub == NOPUSH);
    int n = 0;
    unsigned kth = 0;

    if (!fb) {
        // ---- Phase 2: gather candidate tiles, warp-aggregated compaction ----
        unsigned selm[2];
        selm[0] = __ballot_sync(0xffffffffu, m0v <= tub);
        selm[1] = __ballot_sync(0xffffffffu, m1v <= tub);
        #pragma unroll
        for (int half = 0; half < 2; ++half) {
            unsigned s = selm[half];
            while (s) {
                int c = __ffs(s) - 1; s &= s - 1;
                int tile = half * 32 + c;
                uint4 q = ((const uint4*)rowp)[tile * 32 + lane];
                int jb = tile * 128 + lane * 4;
                unsigned vv[4] = {q.x, q.y, q.z, q.w};
                #pragma unroll
                for (int e = 0; e < 4; ++e) {
                    bool keep = (vv[e] <= tub);
                    unsigned m = __ballot_sync(0xffffffffu, keep);
                    int pos = n + __popc(m & ((1u << lane) - 1u));
                    if (keep && pos < CAPW) { sv[wid][pos] = vv[e]; sj[wid][pos] = jb + e; }
                    n += __popc(m);
                }
            }
        }
        if (n > CAPW) fb = true;
    }

    if (!fb) {
        __syncwarp();
        // ---- Phase 3: exact kk-th among candidates ----
        if (n <= 32) {
            unsigned c = (lane < n) ? sv[wid][lane] : NOPUSH;
            int cls = 0, cle = 0;
            for (int j = 0; j < n; ++j) {
                unsigned b = __shfl_sync(0xffffffffu, c, j);
                cls += (b < c);
                cle += (b <= c);
            }
            bool sel = (cls < kk) && (cle >= kk);
            unsigned ball = __ballot_sync(0xffffffffu, sel);
            kth = __shfl_sync(0xffffffffu, c, __ffs(ball) - 1);
        } else {
            unsigned prefix = 0u;
            for (int b = 30; b >= 0; --b) {
                unsigned tc = prefix | (1u << b);
                int cc = 0;
                for (int p = lane; p < n; p += 32) cc += (sv[wid][p] < tc);
                #pragma unroll
                for (int off = 16; off; off >>= 1) cc += __shfl_xor_sync(0xffffffffu, cc, off);
                if (cc < kk) prefix = tc;
            }
            kth = prefix;
        }
        // ---- Phase 4: strict-< histogram over candidates ----
        for (int p = lane; p < n; p += 32)
            if (sv[wid][p] < kth) atomicAdd(&counts[wid][g_hard[sj[wid][p]]], 1);
    } else {
        // ---- Generic exact path over the materialized row (never hit @k=15)
        unsigned prefix = 0u;
        for (int b = 30; b >= 0; --b) {
            unsigned tc = prefix | (1u << b);
            int cc = 0;
            for (int j = lane; j < B; j += 32)
                cc += (__float_as_uint(rowp[j]) < tc);
            #pragma unroll
            for (int off = 16; off; off >>= 1) cc += __shfl_xor_sync(0xffffffffu, cc, off);
            if (cc < kk) prefix = tc;
        }
        for (int j = lane; j < B; j += 32)
            if (__float_as_uint(rowp[j]) < prefix)
                atomicAdd(&counts[wid][g_hard[j]], 1);
    }
    __syncwarp();

    // ---- entropy ----
    float c0 = (lane < C)      ? (float)counts[wid][lane]      : 0.f;
    float c1 = (lane + 32 < C) ? (float)counts[wid][lane + 32] : 0.f;
    float nn = c0 + c1;
    #pragma unroll
    for (int off = 16; off; off >>= 1) nn += __shfl_xor_sync(0xffffffffu, nn, off);
    float ni = (nn > 1.f) ? nn : 1.f;
    float b0 = c0 / ni, b1 = c1 / ni;
    float h = -b0 * logf(b0 + 1e-5f) - b1 * logf(b1 + 1e-5f);
    #pragma unroll
    for (int off = 16; off; off >>= 1) h += __shfl_xor_sync(0xffffffffu, h, off);
    if (lane == 0) out_ent[row] = h;
}

// ---------------------------------------------------------------------------
__global__ void finalize_kernel(float* __restrict__ out2, int B, int C) {
    int lane = threadIdx.x;
    float g  = (lane < C) ? (float)g_gcounts[lane] : 0.f;
    float gb = g / (float)B;
    float h  = -gb * logf(gb + 1e-5f);
    float p  = (lane < C && g > 0.f) ? 1.f : 0.f;
    #pragma unroll
    for (int off = 16; off; off >>= 1) {
        h += __shfl_xor_sync(0xffffffffu, h, off);
        p += __shfl_xor_sync(0xffffffffu, p, off);
    }
    if (lane == 0) { out2[0] = h; out2[1] = p; }
}

// ---------------------------------------------------------------------------
// Output layout (flattened reference tuple):
//   [0, B*64)            encodings passthrough
//   [B*64, B*64+B)       neighbourhood_entropy
//   [B*64+B]             cluster_size_entropy
//   [B*64+B+1]           n_populated
//   [B*64+B+2, +B)       max_groups
// ---------------------------------------------------------------------------
extern "C" void kernel_launch(void* const* d_in, const int* in_sizes, int n_in,
                              void* d_out, int out_size) {
    const float* E    = (const float*)d_in[0];
    const float* Cat  = (const float*)d_in[1];
    const int*   kptr = (const int*)d_in[2];

    int B = in_sizes[0] / DIMS;
    int C = in_sizes[1] / B;

    float* out      = (float*)d_out;
    float* out_ent  = out + (size_t)B * DIMS;
    float* out_sc   = out_ent + B;
    float* out_maxg = out_sc + 2;

    cudaMemcpyAsync(out, E, (size_t)B * DIMS * sizeof(float),
                    cudaMemcpyDeviceToDevice, 0);

    cudaFuncSetAttribute(mma_gemm_kernel,
                         cudaFuncAttributeMaxDynamicSharedMemorySize, SMEM_BYTES);

    int nb = B / 128;
    int ntri = nb * (nb + 1) / 2;

    convert_kernel<<<(B * DIMS + 255) / 256, 256>>>(E, B);
    stats_kernel<<<(B * 32 + 255) / 256, 256>>>(E, Cat, out_maxg, B, C);
    mma_gemm_kernel<<<ntri, 256, SMEM_BYTES>>>(B);
    select3_kernel<<<(B + 7) / 8, 256>>>(kptr, out_ent, B, C);
    finalize_kernel<<<1, 32>>>(out_sc, B, C);
}